// round 12
// baseline (speedup 1.0000x reference)
#include <cuda_runtime.h>
#include <math.h>

#define N_CLUS 64
#define C_DIM 768
#define B_DIM 8
#define H_IN 32
#define HW 1024                          // 32*32
#define OUT_HW 512
#define PLANE (OUT_HW * OUT_HW)          // 262144
#define NPIX (B_DIM * HW)                // 8192
#define RES_ELEMS ((size_t)B_DIM * N_CLUS * PLANE)   // 134217728
#define CODE_ELEMS ((size_t)B_DIM * C_DIM * HW)      // 6291456
#define KC 32
#define KHALF 384                        // K per sim block

#define ZERO_BLOCKS 192
// zero region = floats [1, 1+RES_ELEMS) of out. Head scalars 1,2,3; aligned
// float4 span floats [4, 134217728) = 33554431 f4s; tail scalar 134217728.
#define NQ4 33554431LL

#define COPY_BLOCKS 128
// copy: dst floats [3, 6291455) as float4 (dst+3 is 16B aligned)
#define COPY_Q4 1572863LL

__device__ float g_nclus[N_CLUS * C_DIM];
__device__ float g_part[2 * 128 * 64 * 64];   // [half][grp][n][px] 4MB
__device__ float g_ssqp[2 * NPIX];            // [half][px]
__device__ int   g_assign[NPIX];
__device__ float g_maxcos[NPIX];

// ---- packed fp32x2 helpers (Blackwell FFMA2) ----
__device__ __forceinline__ unsigned long long splat2(float x) {
    unsigned long long r;
    unsigned u = __float_as_uint(x);
    asm("mov.b64 %0, {%1, %2};" : "=l"(r) : "r"(u), "r"(u));
    return r;
}
__device__ __forceinline__ float2 unpack2(unsigned long long v) {
    unsigned lo, hi;
    asm("mov.b64 {%0, %1}, %2;" : "=r"(lo), "=r"(hi) : "l"(v));
    return make_float2(__uint_as_float(lo), __uint_as_float(hi));
}
#define FMA2(d, a, b) \
    asm("fma.rn.f32x2 %0, %1, %2, %0;" : "+l"(d) : "l"(a), "l"(b))

// ---------------------------------------------------------------------------
// zeroK: bounded-grid streaming zero of the resized region. 192 blocks x 256.
// 0 smem, tiny regs => co-resident with the sim chain on the same SMs.
// ---------------------------------------------------------------------------
__global__ __launch_bounds__(256) void zeroK(float* __restrict__ out) {
    const int tid = threadIdx.x;
    float4* o4 = (float4*)out;               // out is 16B aligned
    const float4 z = make_float4(0.f, 0.f, 0.f, 0.f);
    for (long long q = (long long)blockIdx.x * 256 + tid; q < NQ4;
         q += (long long)ZERO_BLOCKS * 256)
        o4[1 + q] = z;                       // floats [4, 134217728)
    if (blockIdx.x == 0 && tid < 4)
        out[(tid == 3) ? 134217728u : (1u + tid)] = 0.f;
}

// ---------------------------------------------------------------------------
// normK: L2-normalize cluster centroids once. 64 blocks x 256 threads.
// ---------------------------------------------------------------------------
__global__ void normK(const float* __restrict__ clusters) {
    const int r = blockIdx.x;
    __shared__ float red[256];
    float s = 0.f;
    for (int i = threadIdx.x; i < C_DIM; i += 256) {
        float v = clusters[r * C_DIM + i];
        s = fmaf(v, v, s);
    }
    red[threadIdx.x] = s;
    __syncthreads();
    for (int o = 128; o > 0; o >>= 1) {
        if (threadIdx.x < o) red[threadIdx.x] += red[threadIdx.x + o];
        __syncthreads();
    }
    const float inv = 1.f / fmaxf(sqrtf(red[0]), 1e-12f);
    for (int i = threadIdx.x; i < C_DIM; i += 256)
        g_nclus[r * C_DIM + i] = clusters[r * C_DIM + i] * inv;
}

// ---------------------------------------------------------------------------
// simPartK (R11-proven): partial cosine dots over one K-half.
// 256 blocks x 256 thr. blk = grp(128 px-groups of 64) x half(2).
// Thread = 4 px x 4 clusters, FFMA2 inner loop. Epilogue: smem transpose.
// ---------------------------------------------------------------------------
__global__ __launch_bounds__(256) void simPartK(const float* __restrict__ code) {
    const int tid = threadIdx.x;
    const int blk = blockIdx.x;
    const int half = blk & 1;
    const int grp = blk >> 1;

    __shared__ __align__(16) float codeS[KC][64];
    __shared__ __align__(16) float clusG[16][132];   // [ng][c*4+j], pad->132
    __shared__ float pT[64 * 65];                    // [n][px], pitch 65

    const int b = grp >> 4;                  // 16 groups per image
    const int hwbase = (grp & 15) * 64;
    const int pid = tid >> 4;                // pixel quad: px 4*pid..4*pid+3
    const int ng = tid & 15;                 // cluster group: n = 4*ng..4*ng+3
    const float* codeb = code + (size_t)b * C_DIM * HW + hwbase;
    const int cbase = half * KHALF;

    unsigned long long acc2[4][2];
#pragma unroll
    for (int p = 0; p < 4; ++p) { acc2[p][0] = 0ull; acc2[p][1] = 0ull; }
    float ssq[4] = {0.f, 0.f, 0.f, 0.f};

    for (int cc = 0; cc < KHALF; cc += KC) {
        const int c0 = cbase + cc;
#pragma unroll
        for (int k = 0; k < 8; ++k) {        // stage code [KC][64], coalesced
            int idx = tid + k * 256;
            int c = idx >> 6, px = idx & 63;
            codeS[c][px] = codeb[(size_t)(c0 + c) * HW + px];
        }
#pragma unroll
        for (int k = 0; k < 8; ++k) {        // stage pre-normed clusters
            int idx = tid + k * 256;
            int g = idx >> 7, rr = idx & 127;
            int j = rr & 3, c = rr >> 2;
            clusG[g][c * 4 + j] = g_nclus[(g * 4 + j) * C_DIM + c0 + c];
        }
        __syncthreads();

#pragma unroll 4
        for (int c = 0; c < KC; ++c) {
            float4 a = *(const float4*)&codeS[c][4 * pid];
            ulonglong2 bp = *(const ulonglong2*)&clusG[ng][4 * c];
            if (ng == 0) {                   // fold feature sumsq (this half)
                ssq[0] = fmaf(a.x, a.x, ssq[0]);
                ssq[1] = fmaf(a.y, a.y, ssq[1]);
                ssq[2] = fmaf(a.z, a.z, ssq[2]);
                ssq[3] = fmaf(a.w, a.w, ssq[3]);
            }
            unsigned long long ax = splat2(a.x), ay = splat2(a.y);
            unsigned long long az = splat2(a.z), aw = splat2(a.w);
            FMA2(acc2[0][0], ax, bp.x);  FMA2(acc2[0][1], ax, bp.y);
            FMA2(acc2[1][0], ay, bp.x);  FMA2(acc2[1][1], ay, bp.y);
            FMA2(acc2[2][0], az, bp.x);  FMA2(acc2[2][1], az, bp.y);
            FMA2(acc2[3][0], aw, bp.x);  FMA2(acc2[3][1], aw, bp.y);
        }
        __syncthreads();
    }

    // epilogue: transpose to n-major in smem, then coalesced global write
#pragma unroll
    for (int p = 0; p < 4; ++p) {
        float2 j01 = unpack2(acc2[p][0]);
        float2 j23 = unpack2(acc2[p][1]);
        const int px = 4 * pid + p;
        pT[(4 * ng + 0) * 65 + px] = j01.x;
        pT[(4 * ng + 1) * 65 + px] = j01.y;
        pT[(4 * ng + 2) * 65 + px] = j23.x;
        pT[(4 * ng + 3) * 65 + px] = j23.y;
        if (ng == 0) g_ssqp[half * NPIX + grp * 64 + px] = ssq[p];
    }
    __syncthreads();

    float* dst = g_part + (size_t)(half * 128 + grp) * 4096;
#pragma unroll
    for (int k = 0; k < 16; ++k) {
        int idx = tid + k * 256;
        int n = idx >> 6, px = idx & 63;
        dst[idx] = pT[n * 65 + px];
    }
}

// ---------------------------------------------------------------------------
// argmaxK: combine K-halves, per-pixel argmax + maxcos. 32 blocks x 256 thr.
// ---------------------------------------------------------------------------
__global__ void argmaxK() {
    const int px = blockIdx.x * 256 + threadIdx.x;
    const int grp = px >> 6, pxl = px & 63;
    const float* p0 = g_part + (size_t)grp * 4096 + pxl;
    const float* p1 = g_part + (size_t)(128 + grp) * 4096 + pxl;

    float mv = -3.4e38f;
    int mn = 0;
#pragma unroll 8
    for (int n = 0; n < N_CLUS; ++n) {       // ascending n, strict > => first-max
        float s = __ldg(p0 + n * 64) + __ldg(p1 + n * 64);
        if (s > mv) { mv = s; mn = n; }
    }
    const float ssq = g_ssqp[px] + g_ssqp[NPIX + px];
    g_assign[px] = mn;
    g_maxcos[px] = mv / fmaxf(sqrtf(ssq), 1e-12f);
}

// ---------------------------------------------------------------------------
// lossK: deterministic reduction of max cosine sims. 1 block x 256 thr.
// ---------------------------------------------------------------------------
__global__ void lossK(float* __restrict__ out) {
    __shared__ float red[256];
    float s = 0.f;
    for (int i = threadIdx.x; i < NPIX; i += 256) s += g_maxcos[i];
    red[threadIdx.x] = s;
    __syncthreads();
    for (int o = 128; o > 0; o >>= 1) {
        if (threadIdx.x < o) red[threadIdx.x] += red[threadIdx.x + o];
        __syncthreads();
    }
    if (threadIdx.x == 0) out[0] = -red[0] / (float)NPIX;
}

// ---------------------------------------------------------------------------
// copyK: code passthrough, vectorized. 128 blocks x 256 thr.
// dst = out+1+RES; dst+3 is 16B aligned -> STG.128 body, 4 edge scalars.
// ---------------------------------------------------------------------------
__global__ __launch_bounds__(256) void copyK(const float* __restrict__ code,
                                             float* __restrict__ out) {
    const int tid = threadIdx.x;
    float* dst = out + 1 + RES_ELEMS;
    if (blockIdx.x == 0 && tid < 4) {
        long long i = (tid == 3) ? (long long)(CODE_ELEMS - 1) : tid;
        dst[i] = __ldg(code + i);
    }
    for (long long q = (long long)blockIdx.x * 256 + tid; q < COPY_Q4;
         q += (long long)COPY_BLOCKS * 256) {
        const float* s = code + 3 + 4 * q;
        float4 v = make_float4(__ldg(s), __ldg(s + 1), __ldg(s + 2), __ldg(s + 3));
        *(float4*)(dst + 3 + 4 * q) = v;
    }
}

// ---------------------------------------------------------------------------
// scatterK (R9-proven): sparse bilinear scatter over the pre-zeroed output.
// Grid (2, 512, 8) x 256 thr: thread = one x of one (b, y) row.
// ---------------------------------------------------------------------------
__global__ __launch_bounds__(256) void scatterK(float* __restrict__ out) {
    const int b = blockIdx.z;
    const int y = blockIdx.y;
    const int x = blockIdx.x * 256 + threadIdx.x;

    const float fy = (y + 0.5f) * 0.0625f - 0.5f;
    const float y0f = floorf(fy);
    const float wy1 = fy - y0f, wy0 = 1.f - wy1;
    const int y0 = (int)y0f;
    const int ylo = max(y0, 0), yhi = min(y0 + 1, H_IN - 1);
    const int* A0 = g_assign + b * HW + ylo * H_IN;
    const int* A1 = g_assign + b * HW + yhi * H_IN;

    const float fx = (x + 0.5f) * 0.0625f - 0.5f;
    const float x0f = floorf(fx);
    const float wx1 = fx - x0f, wx0 = 1.f - wx1;
    const int x0 = (int)x0f;
    const int xlo = max(x0, 0), xhi = min(x0 + 1, H_IN - 1);

    int nn[4]; float w[4];
    nn[0] = __ldg(A0 + xlo); w[0] = wy0 * wx0;
    nn[1] = __ldg(A0 + xhi); w[1] = wy0 * wx1;
    nn[2] = __ldg(A1 + xlo); w[2] = wy1 * wx0;
    nn[3] = __ldg(A1 + xhi); w[3] = wy1 * wx1;

    bool v[4] = {true, true, true, true};
#pragma unroll
    for (int i = 1; i < 4; ++i)
#pragma unroll
        for (int j = 0; j < i; ++j)
            if (v[i] && v[j] && nn[i] == nn[j]) { w[j] += w[i]; v[i] = false; }

    float* base = out + 1 + (size_t)b * N_CLUS * PLANE + (size_t)y * OUT_HW + x;
#pragma unroll
    for (int i = 0; i < 4; ++i)
        if (v[i]) base[(size_t)nn[i] * PLANE] = w[i];
}

// ---------------------------------------------------------------------------
// Two-stream graph (bounded grids => genuine SM sharing):
//   s2: zeroK (192 blocks, 537MB streaming zero)
//   s0: normK -> simPartK -> argmaxK -> lossK -> copyK   (hides under zeroK)
//   join: scatterK (needs zeroed canvas + assignments)
// out layout = [loss(1)] [resized(134217728)] [code(6291456)]
// ---------------------------------------------------------------------------
extern "C" void kernel_launch(void* const* d_in, const int* in_sizes, int n_in,
                              void* d_out, int out_size) {
    const float* code = (const float*)d_in[0];
    const float* clusters = (const float*)d_in[1];
    float* out = (float*)d_out;

    static cudaStream_t s2 = 0;
    static cudaEvent_t evF = 0, evJ = 0;
    if (s2 == 0) {
        cudaStreamCreateWithFlags(&s2, cudaStreamNonBlocking);
        cudaEventCreateWithFlags(&evF, cudaEventDisableTiming);
        cudaEventCreateWithFlags(&evJ, cudaEventDisableTiming);
    }

    // fork
    cudaEventRecord(evF, 0);
    cudaStreamWaitEvent(s2, evF, 0);
    zeroK<<<ZERO_BLOCKS, 256, 0, s2>>>(out);

    // sim chain + copy on default stream (co-resident with zeroK)
    normK<<<64, 256>>>(clusters);
    simPartK<<<256, 256>>>(code);
    argmaxK<<<32, 256>>>();
    lossK<<<1, 256>>>(out);
    copyK<<<COPY_BLOCKS, 256>>>(code, out);

    // join: scatter needs both branches done
    cudaEventRecord(evJ, s2);
    cudaStreamWaitEvent(0, evJ, 0);
    dim3 gs(2, OUT_HW, B_DIM);
    scatterK<<<gs, 256>>>(out);
}

// round 13
// speedup vs baseline: 1.2054x; 1.2054x over previous
#include <cuda_runtime.h>
#include <math.h>

#define N_CLUS 64
#define C_DIM 768
#define B_DIM 8
#define H_IN 32
#define HW 1024                          // 32*32
#define OUT_HW 512
#define PLANE (OUT_HW * OUT_HW)          // 262144
#define NPIX (B_DIM * HW)                // 8192
#define RES_ELEMS ((size_t)B_DIM * N_CLUS * PLANE)   // 134217728
#define CODE_ELEMS ((size_t)B_DIM * C_DIM * HW)      // 6291456
#define KC 32
#define KQ 192                           // K per sim block (4-way split)

#define FILL_BLOCKS 4096                 // writeK: one per (b, y)
#define COPY_BLOCKS 128
#define W_BLOCKS (FILL_BLOCKS + COPY_BLOCKS + 1)   // +1 loss block
// copy: dst floats [3, 6291455) as float4 (dst+3 is 16B aligned)
#define COPY_Q4 1572863LL

__device__ float g_nclus[N_CLUS * C_DIM];
__device__ float g_part[4 * 128 * 64 * 64];   // [quarter][grp][n][px] 8MB
__device__ float g_ssqp[4 * NPIX];            // [quarter][px]
__device__ int   g_assign[NPIX];
__device__ float g_maxcos[NPIX];

// ---- packed fp32x2 helpers (Blackwell FFMA2) ----
__device__ __forceinline__ unsigned long long splat2(float x) {
    unsigned long long r;
    unsigned u = __float_as_uint(x);
    asm("mov.b64 %0, {%1, %2};" : "=l"(r) : "r"(u), "r"(u));
    return r;
}
__device__ __forceinline__ float2 unpack2(unsigned long long v) {
    unsigned lo, hi;
    asm("mov.b64 {%0, %1}, %2;" : "=r"(lo), "=r"(hi) : "l"(v));
    return make_float2(__uint_as_float(lo), __uint_as_float(hi));
}
#define FMA2(d, a, b) \
    asm("fma.rn.f32x2 %0, %1, %2, %0;" : "+l"(d) : "l"(a), "l"(b))

// ---------------------------------------------------------------------------
// normK: L2-normalize cluster centroids once. 64 blocks x 256 threads.
// ---------------------------------------------------------------------------
__global__ void normK(const float* __restrict__ clusters) {
    const int r = blockIdx.x;
    __shared__ float red[256];
    float s = 0.f;
    for (int i = threadIdx.x; i < C_DIM; i += 256) {
        float v = clusters[r * C_DIM + i];
        s = fmaf(v, v, s);
    }
    red[threadIdx.x] = s;
    __syncthreads();
    for (int o = 128; o > 0; o >>= 1) {
        if (threadIdx.x < o) red[threadIdx.x] += red[threadIdx.x + o];
        __syncthreads();
    }
    const float inv = 1.f / fmaxf(sqrtf(red[0]), 1e-12f);
    for (int i = threadIdx.x; i < C_DIM; i += 256)
        g_nclus[r * C_DIM + i] = clusters[r * C_DIM + i] * inv;
}

// ---------------------------------------------------------------------------
// simPartK: partial cosine dots over one K-quarter. 512 blocks x 256 thr.
// blk = grp(128 px-groups of 64) x quarter(4). Thread = 4 px x 4 clusters,
// R7/R11-proven FFMA2 inner loop. Epilogue: smem transpose -> n-major.
// ---------------------------------------------------------------------------
__global__ __launch_bounds__(256) void simPartK(const float* __restrict__ code) {
    const int tid = threadIdx.x;
    const int blk = blockIdx.x;
    const int qtr = blk & 3;
    const int grp = blk >> 2;

    __shared__ __align__(16) float codeS[KC][64];
    __shared__ __align__(16) float clusG[16][132];   // [ng][c*4+j], pad->132
    __shared__ float pT[64 * 65];                    // [n][px], pitch 65

    const int b = grp >> 4;                  // 16 groups per image
    const int hwbase = (grp & 15) * 64;
    const int pid = tid >> 4;                // pixel quad: px 4*pid..4*pid+3
    const int ng = tid & 15;                 // cluster group: n = 4*ng..4*ng+3
    const float* codeb = code + (size_t)b * C_DIM * HW + hwbase;
    const int cbase = qtr * KQ;

    unsigned long long acc2[4][2];
#pragma unroll
    for (int p = 0; p < 4; ++p) { acc2[p][0] = 0ull; acc2[p][1] = 0ull; }
    float ssq[4] = {0.f, 0.f, 0.f, 0.f};

    for (int cc = 0; cc < KQ; cc += KC) {
        const int c0 = cbase + cc;
#pragma unroll
        for (int k = 0; k < 8; ++k) {        // stage code [KC][64], coalesced
            int idx = tid + k * 256;
            int c = idx >> 6, px = idx & 63;
            codeS[c][px] = codeb[(size_t)(c0 + c) * HW + px];
        }
#pragma unroll
        for (int k = 0; k < 8; ++k) {        // stage pre-normed clusters
            int idx = tid + k * 256;
            int g = idx >> 7, rr = idx & 127;
            int j = rr & 3, c = rr >> 2;
            clusG[g][c * 4 + j] = g_nclus[(g * 4 + j) * C_DIM + c0 + c];
        }
        __syncthreads();

#pragma unroll 4
        for (int c = 0; c < KC; ++c) {
            float4 a = *(const float4*)&codeS[c][4 * pid];
            ulonglong2 bp = *(const ulonglong2*)&clusG[ng][4 * c];
            if (ng == 0) {                   // fold feature sumsq (this quarter)
                ssq[0] = fmaf(a.x, a.x, ssq[0]);
                ssq[1] = fmaf(a.y, a.y, ssq[1]);
                ssq[2] = fmaf(a.z, a.z, ssq[2]);
                ssq[3] = fmaf(a.w, a.w, ssq[3]);
            }
            unsigned long long ax = splat2(a.x), ay = splat2(a.y);
            unsigned long long az = splat2(a.z), aw = splat2(a.w);
            FMA2(acc2[0][0], ax, bp.x);  FMA2(acc2[0][1], ax, bp.y);
            FMA2(acc2[1][0], ay, bp.x);  FMA2(acc2[1][1], ay, bp.y);
            FMA2(acc2[2][0], az, bp.x);  FMA2(acc2[2][1], az, bp.y);
            FMA2(acc2[3][0], aw, bp.x);  FMA2(acc2[3][1], aw, bp.y);
        }
        __syncthreads();
    }

    // epilogue: transpose to n-major in smem, then coalesced global write
#pragma unroll
    for (int p = 0; p < 4; ++p) {
        float2 j01 = unpack2(acc2[p][0]);
        float2 j23 = unpack2(acc2[p][1]);
        const int px = 4 * pid + p;
        pT[(4 * ng + 0) * 65 + px] = j01.x;
        pT[(4 * ng + 1) * 65 + px] = j01.y;
        pT[(4 * ng + 2) * 65 + px] = j23.x;
        pT[(4 * ng + 3) * 65 + px] = j23.y;
        if (ng == 0) g_ssqp[qtr * NPIX + grp * 64 + px] = ssq[p];
    }
    __syncthreads();

    float* dst = g_part + (size_t)(qtr * 128 + grp) * 4096;
#pragma unroll
    for (int k = 0; k < 16; ++k) {
        int idx = tid + k * 256;
        int n = idx >> 6, px = idx & 63;
        dst[idx] = pT[n * 65 + px];
    }
}

// ---------------------------------------------------------------------------
// argmaxK: combine 4 K-quarters, per-pixel argmax + maxcos.
// 128 blocks (one per px-group) x 256 thr; q = tid>>6 scans 16 n's,
// smem reduce in ascending q (strict > => global first-max tiebreak).
// ---------------------------------------------------------------------------
__global__ __launch_bounds__(256) void argmaxK() {
    const int grp = blockIdx.x;
    const int q = threadIdx.x >> 6;          // n-quarter 0..3
    const int pxl = threadIdx.x & 63;

    __shared__ float smv[4][64];
    __shared__ int   smn[4][64];

    float mv = -3.4e38f;
    int mn = 0;
#pragma unroll 4
    for (int i = 0; i < 16; ++i) {           // ascending n within quarter
        const int n = q * 16 + i;
        float s = 0.f;
#pragma unroll
        for (int p = 0; p < 4; ++p)
            s += __ldg(g_part + (size_t)(p * 128 + grp) * 4096 + n * 64 + pxl);
        if (s > mv) { mv = s; mn = n; }
    }
    smv[q][pxl] = mv;
    smn[q][pxl] = mn;
    __syncthreads();

    if (threadIdx.x < 64) {                  // q==0 lanes finalize px = pxl
        float best = smv[0][pxl];
        int bn = smn[0][pxl];
#pragma unroll
        for (int g = 1; g < 4; ++g)          // ascending q => first-max
            if (smv[g][pxl] > best) { best = smv[g][pxl]; bn = smn[g][pxl]; }
        float ssq = 0.f;
#pragma unroll
        for (int p = 0; p < 4; ++p) ssq += g_ssqp[p * NPIX + grp * 64 + pxl];
        const int gp = grp * 64 + pxl;
        g_assign[gp] = bn;
        g_maxcos[gp] = best / fmaxf(sqrtf(ssq), 1e-12f);
    }
}

// ---------------------------------------------------------------------------
// writeK (R11-proven, 111.6us): single-pass direct write + copy + loss.
//   blocks [0,4096):      (b,y) row across all 64 planes. Thread owns one
//                         aligned float4 slot; precomputes bilinear candidates
//                         + 64-bit nonzero-plane mask; 1 STG.128 per plane.
//   blocks [4096,4224):   code passthrough copy (vectorized stores)
//   block  4224:          deterministic loss reduction
// ---------------------------------------------------------------------------
__global__ __launch_bounds__(128) void writeK(const float* __restrict__ code,
                                              float* __restrict__ out) {
    const int blk = blockIdx.x;
    const int tid = threadIdx.x;

    if (blk >= FILL_BLOCKS) {
        if (blk < FILL_BLOCKS + COPY_BLOCKS) {
            // ---- code passthrough: dst+3 is 16B aligned -> STG.128 body ----
            const int id = blk - FILL_BLOCKS;
            float* dst = out + 1 + RES_ELEMS;
            if (id == 0 && tid < 4) {
                int i = (tid == 3) ? (int)(CODE_ELEMS - 1) : tid;
                dst[i] = __ldg(code + i);
            }
            for (long long q = (long long)id * 128 + tid; q < COPY_Q4;
                 q += (long long)COPY_BLOCKS * 128) {
                const float* s = code + 3 + 4 * q;
                float4 v = make_float4(__ldg(s), __ldg(s + 1),
                                       __ldg(s + 2), __ldg(s + 3));
                *(float4*)(dst + 3 + 4 * q) = v;
            }
        } else {
            // ---- loss ----
            __shared__ float red[128];
            float s = 0.f;
            for (int i = tid; i < NPIX; i += 128) s += g_maxcos[i];
            red[tid] = s;
            __syncthreads();
            for (int o = 64; o > 0; o >>= 1) {
                if (tid < o) red[tid] += red[tid + o];
                __syncthreads();
            }
            if (tid == 0) out[0] = -red[0] / (float)NPIX;
        }
        return;
    }

    // ---- fill+scatter for one (b, y) ----
    const int b = blk >> 9;
    const int y = blk & 511;

    const float fy = (y + 0.5f) * 0.0625f - 0.5f;
    const float y0f = floorf(fy);
    const float wy1 = fy - y0f, wy0 = 1.f - wy1;
    const int y0 = (int)y0f;
    const int ylo = max(y0, 0), yhi = min(y0 + 1, H_IN - 1);
    const int* A0 = g_assign + b * HW + ylo * H_IN;
    const int* A1 = g_assign + b * HW + yhi * H_IN;

    // thread t<127 owns aligned f4 at rel floats [3+4t, 7+4t); t==127 owns
    // the 4 edge scalars x = {0,1,2,511}. (row base = out+1+... => +3 is 16B
    // aligned.)
    int xs[4];
    if (tid < 127) {
#pragma unroll
        for (int k = 0; k < 4; ++k) xs[k] = 4 * tid + 3 + k;
    } else {
        xs[0] = 0; xs[1] = 1; xs[2] = 2; xs[3] = 511;
    }

    int   id[4][4];
    float w[4][4];
    unsigned long long mask = 0ull;
#pragma unroll
    for (int k = 0; k < 4; ++k) {
        const int x = xs[k];
        const float fx = (x + 0.5f) * 0.0625f - 0.5f;
        const float x0f = floorf(fx);
        const float wx1 = fx - x0f, wx0 = 1.f - wx1;
        const int x0 = (int)x0f;
        const int xlo = max(x0, 0), xhi = min(x0 + 1, H_IN - 1);
        id[k][0] = __ldg(A0 + xlo); w[k][0] = wy0 * wx0;
        id[k][1] = __ldg(A0 + xhi); w[k][1] = wy0 * wx1;
        id[k][2] = __ldg(A1 + xlo); w[k][2] = wy1 * wx0;
        id[k][3] = __ldg(A1 + xhi); w[k][3] = wy1 * wx1;
        mask |= 1ull << id[k][0];
        mask |= 1ull << id[k][1];
        mask |= 1ull << id[k][2];
        mask |= 1ull << id[k][3];
    }

    float* base = out + 1 + (size_t)b * N_CLUS * PLANE + (size_t)y * OUT_HW;
    const int slot = 3 + 4 * tid;

#pragma unroll 4
    for (int n = 0; n < N_CLUS; ++n) {
        float4 v = make_float4(0.f, 0.f, 0.f, 0.f);
        if ((mask >> n) & 1ull) {
            float r[4];
#pragma unroll
            for (int k = 0; k < 4; ++k) {
                float s = 0.f;
#pragma unroll
                for (int q = 0; q < 4; ++q)
                    s += (id[k][q] == n) ? w[k][q] : 0.f;
                r[k] = s;
            }
            v = make_float4(r[0], r[1], r[2], r[3]);
        }
        float* row = base + (size_t)n * PLANE;
        if (tid < 127) {
            *(float4*)(row + slot) = v;      // plain STG.128
        } else {
            row[0] = v.x;
            row[1] = v.y;
            row[2] = v.z;
            row[511] = v.w;
        }
    }
}

// ---------------------------------------------------------------------------
// out layout = [loss(1)] [resized(134217728)] [code(6291456)]
// ---------------------------------------------------------------------------
extern "C" void kernel_launch(void* const* d_in, const int* in_sizes, int n_in,
                              void* d_out, int out_size) {
    const float* code = (const float*)d_in[0];
    const float* clusters = (const float*)d_in[1];
    float* out = (float*)d_out;

    normK<<<64, 256>>>(clusters);
    simPartK<<<512, 256>>>(code);
    argmaxK<<<128, 256>>>();
    writeK<<<W_BLOCKS, 128>>>(code, out);
}

// round 14
// speedup vs baseline: 1.2412x; 1.0297x over previous
#include <cuda_runtime.h>
#include <math.h>

#define N_CLUS 64
#define C_DIM 768
#define B_DIM 8
#define H_IN 32
#define HW 1024                          // 32*32
#define OUT_HW 512
#define PLANE (OUT_HW * OUT_HW)          // 262144
#define NPIX (B_DIM * HW)                // 8192
#define RES_ELEMS ((size_t)B_DIM * N_CLUS * PLANE)   // 134217728
#define CODE_ELEMS ((size_t)B_DIM * C_DIM * HW)      // 6291456
#define KC 64                            // staging chunk (3 per quarter)
#define KQ 192                           // K per sim block (4-way split)

#define FILL_BLOCKS 4096                 // writeK: one per (b, y)
#define COPY_BLOCKS 128
#define W_BLOCKS (FILL_BLOCKS + COPY_BLOCKS + 1)   // +1 loss block
// copy: dst floats [3, 6291455) as float4 (dst+3 is 16B aligned)
#define COPY_Q4 1572863LL

__device__ float g_nclus[N_CLUS * C_DIM];
__device__ float g_part[4 * 128 * 64 * 64];   // [quarter][grp][n][px] 8MB
__device__ float g_ssqp[4 * NPIX];            // [quarter][px]
__device__ int   g_assign[NPIX];
__device__ float g_maxcos[NPIX];
__device__ int   g_cnt[128];                  // per-grp arrival counters (self-resetting)

// ---- packed fp32x2 helpers (Blackwell FFMA2) ----
__device__ __forceinline__ unsigned long long splat2(float x) {
    unsigned long long r;
    unsigned u = __float_as_uint(x);
    asm("mov.b64 %0, {%1, %2};" : "=l"(r) : "r"(u), "r"(u));
    return r;
}
__device__ __forceinline__ float2 unpack2(unsigned long long v) {
    unsigned lo, hi;
    asm("mov.b64 {%0, %1}, %2;" : "=r"(lo), "=r"(hi) : "l"(v));
    return make_float2(__uint_as_float(lo), __uint_as_float(hi));
}
#define FMA2(d, a, b) \
    asm("fma.rn.f32x2 %0, %1, %2, %0;" : "+l"(d) : "l"(a), "l"(b))

// ---------------------------------------------------------------------------
// normK: L2-normalize cluster centroids once. 64 blocks x 256 threads.
// ---------------------------------------------------------------------------
__global__ void normK(const float* __restrict__ clusters) {
    const int r = blockIdx.x;
    __shared__ float red[256];
    float s = 0.f;
    for (int i = threadIdx.x; i < C_DIM; i += 256) {
        float v = clusters[r * C_DIM + i];
        s = fmaf(v, v, s);
    }
    red[threadIdx.x] = s;
    __syncthreads();
    for (int o = 128; o > 0; o >>= 1) {
        if (threadIdx.x < o) red[threadIdx.x] += red[threadIdx.x + o];
        __syncthreads();
    }
    const float inv = 1.f / fmaxf(sqrtf(red[0]), 1e-12f);
    for (int i = threadIdx.x; i < C_DIM; i += 256)
        g_nclus[r * C_DIM + i] = clusters[r * C_DIM + i] * inv;
}

// ---------------------------------------------------------------------------
// simPartK: partial cosine dots over one K-quarter + fused per-group argmax.
// 512 blocks x 256 thr. blk = grp(128 px-groups of 64) x quarter(4).
// Thread = 4 px x 4 clusters, FFMA2 inner loop, KC=64 chunks (3 barriers).
// Last-arriving block of each grp performs the argmax (fence+atomic handoff).
// ---------------------------------------------------------------------------
__global__ __launch_bounds__(256) void simPartK(const float* __restrict__ code) {
    const int tid = threadIdx.x;
    const int blk = blockIdx.x;
    const int qtr = blk & 3;
    const int grp = blk >> 2;

    __shared__ __align__(16) float codeS[KC][64];    // 16KB
    __shared__ __align__(16) float clusG[16][260];   // [ng][c*4+j], pad->260
    __shared__ float pT[64 * 65];                    // [n][px], pitch 65
    __shared__ float smv[4][64];
    __shared__ int   smn[4][64];
    __shared__ int   isLast;

    const int b = grp >> 4;                  // 16 groups per image
    const int hwbase = (grp & 15) * 64;
    const int pid = tid >> 4;                // pixel quad: px 4*pid..4*pid+3
    const int ng = tid & 15;                 // cluster group: n = 4*ng..4*ng+3
    const float* codeb = code + (size_t)b * C_DIM * HW + hwbase;
    const int cbase = qtr * KQ;

    unsigned long long acc2[4][2];
#pragma unroll
    for (int p = 0; p < 4; ++p) { acc2[p][0] = 0ull; acc2[p][1] = 0ull; }
    float ssq[4] = {0.f, 0.f, 0.f, 0.f};

    for (int cc = 0; cc < KQ; cc += KC) {
        const int c0 = cbase + cc;
#pragma unroll
        for (int k = 0; k < 16; ++k) {       // stage code [KC][64], coalesced
            int idx = tid + k * 256;
            int c = idx >> 6, px = idx & 63;
            codeS[c][px] = codeb[(size_t)(c0 + c) * HW + px];
        }
#pragma unroll
        for (int k = 0; k < 16; ++k) {       // stage pre-normed clusters
            int idx = tid + k * 256;
            int g = idx >> 8, rr = idx & 255;
            int j = rr & 3, c = rr >> 2;
            clusG[g][c * 4 + j] = g_nclus[(g * 4 + j) * C_DIM + c0 + c];
        }
        __syncthreads();

#pragma unroll 4
        for (int c = 0; c < KC; ++c) {
            float4 a = *(const float4*)&codeS[c][4 * pid];
            ulonglong2 bp = *(const ulonglong2*)&clusG[ng][4 * c];
            if (ng == 0) {                   // fold feature sumsq (this quarter)
                ssq[0] = fmaf(a.x, a.x, ssq[0]);
                ssq[1] = fmaf(a.y, a.y, ssq[1]);
                ssq[2] = fmaf(a.z, a.z, ssq[2]);
                ssq[3] = fmaf(a.w, a.w, ssq[3]);
            }
            unsigned long long ax = splat2(a.x), ay = splat2(a.y);
            unsigned long long az = splat2(a.z), aw = splat2(a.w);
            FMA2(acc2[0][0], ax, bp.x);  FMA2(acc2[0][1], ax, bp.y);
            FMA2(acc2[1][0], ay, bp.x);  FMA2(acc2[1][1], ay, bp.y);
            FMA2(acc2[2][0], az, bp.x);  FMA2(acc2[2][1], az, bp.y);
            FMA2(acc2[3][0], aw, bp.x);  FMA2(acc2[3][1], aw, bp.y);
        }
        __syncthreads();
    }

    // epilogue: transpose to n-major in smem, then coalesced global write
#pragma unroll
    for (int p = 0; p < 4; ++p) {
        float2 j01 = unpack2(acc2[p][0]);
        float2 j23 = unpack2(acc2[p][1]);
        const int px = 4 * pid + p;
        pT[(4 * ng + 0) * 65 + px] = j01.x;
        pT[(4 * ng + 1) * 65 + px] = j01.y;
        pT[(4 * ng + 2) * 65 + px] = j23.x;
        pT[(4 * ng + 3) * 65 + px] = j23.y;
        if (ng == 0) g_ssqp[qtr * NPIX + grp * 64 + px] = ssq[p];
    }
    __syncthreads();

    float* dst = g_part + (size_t)(qtr * 128 + grp) * 4096;
#pragma unroll
    for (int k = 0; k < 16; ++k) {
        int idx = tid + k * 256;
        int n = idx >> 6, px = idx & 63;
        dst[idx] = pT[n * 65 + px];
    }

    // ---- arrival handoff: last quarter-block of this grp does the argmax ----
    __syncthreads();                         // all epilogue stores issued
    if (tid == 0) {
        __threadfence();                     // publish g_part/g_ssqp (release)
        int old = atomicAdd(&g_cnt[grp], 1);
        isLast = (old == 3);
        if (isLast) __threadfence();         // acquire: others' writes visible
    }
    __syncthreads();
    if (!isLast) return;

    // fused argmax for this grp (identical math to R13 argmaxK)
    {
        const int q = tid >> 6;              // n-quarter 0..3
        const int pxl = tid & 63;
        float mv = -3.4e38f;
        int mn = 0;
#pragma unroll 4
        for (int i = 0; i < 16; ++i) {       // ascending n within quarter
            const int n = q * 16 + i;
            float s = 0.f;
#pragma unroll
            for (int p = 0; p < 4; ++p)
                s += __ldcg(g_part + (size_t)(p * 128 + grp) * 4096 + n * 64 + pxl);
            if (s > mv) { mv = s; mn = n; }
        }
        smv[q][pxl] = mv;
        smn[q][pxl] = mn;
        __syncthreads();

        if (tid < 64) {                      // finalize px = pxl
            float best = smv[0][pxl];
            int bn = smn[0][pxl];
#pragma unroll
            for (int g = 1; g < 4; ++g)      // ascending q => first-max
                if (smv[g][pxl] > best) { best = smv[g][pxl]; bn = smn[g][pxl]; }
            float ssqt = 0.f;
#pragma unroll
            for (int p = 0; p < 4; ++p)
                ssqt += __ldcg(g_ssqp + p * NPIX + grp * 64 + pxl);
            const int gp = grp * 64 + pxl;
            g_assign[gp] = bn;
            g_maxcos[gp] = best / fmaxf(sqrtf(ssqt), 1e-12f);
        }
        if (tid == 0) g_cnt[grp] = 0;        // reset for next graph replay
    }
}

// ---------------------------------------------------------------------------
// writeK (R11/R13-proven): single-pass direct write + copy + loss.
//   blocks [0,4096):      (b,y) row across all 64 planes. Thread owns one
//                         aligned float4 slot; precomputes bilinear candidates
//                         + 64-bit nonzero-plane mask; 1 STG.128 per plane.
//   blocks [4096,4224):   code passthrough copy (vectorized stores)
//   block  4224:          deterministic loss reduction
// ---------------------------------------------------------------------------
__global__ __launch_bounds__(128) void writeK(const float* __restrict__ code,
                                              float* __restrict__ out) {
    const int blk = blockIdx.x;
    const int tid = threadIdx.x;

    if (blk >= FILL_BLOCKS) {
        if (blk < FILL_BLOCKS + COPY_BLOCKS) {
            // ---- code passthrough: dst+3 is 16B aligned -> STG.128 body ----
            const int id = blk - FILL_BLOCKS;
            float* dst = out + 1 + RES_ELEMS;
            if (id == 0 && tid < 4) {
                int i = (tid == 3) ? (int)(CODE_ELEMS - 1) : tid;
                dst[i] = __ldg(code + i);
            }
            for (long long q = (long long)id * 128 + tid; q < COPY_Q4;
                 q += (long long)COPY_BLOCKS * 128) {
                const float* s = code + 3 + 4 * q;
                float4 v = make_float4(__ldg(s), __ldg(s + 1),
                                       __ldg(s + 2), __ldg(s + 3));
                *(float4*)(dst + 3 + 4 * q) = v;
            }
        } else {
            // ---- loss ----
            __shared__ float red[128];
            float s = 0.f;
            for (int i = tid; i < NPIX; i += 128) s += g_maxcos[i];
            red[tid] = s;
            __syncthreads();
            for (int o = 64; o > 0; o >>= 1) {
                if (tid < o) red[tid] += red[tid + o];
                __syncthreads();
            }
            if (tid == 0) out[0] = -red[0] / (float)NPIX;
        }
        return;
    }

    // ---- fill+scatter for one (b, y) ----
    const int b = blk >> 9;
    const int y = blk & 511;

    const float fy = (y + 0.5f) * 0.0625f - 0.5f;
    const float y0f = floorf(fy);
    const float wy1 = fy - y0f, wy0 = 1.f - wy1;
    const int y0 = (int)y0f;
    const int ylo = max(y0, 0), yhi = min(y0 + 1, H_IN - 1);
    const int* A0 = g_assign + b * HW + ylo * H_IN;
    const int* A1 = g_assign + b * HW + yhi * H_IN;

    // thread t<127 owns aligned f4 at rel floats [3+4t, 7+4t); t==127 owns
    // the 4 edge scalars x = {0,1,2,511}. (row base = out+1+... => +3 is 16B
    // aligned.)
    int xs[4];
    if (tid < 127) {
#pragma unroll
        for (int k = 0; k < 4; ++k) xs[k] = 4 * tid + 3 + k;
    } else {
        xs[0] = 0; xs[1] = 1; xs[2] = 2; xs[3] = 511;
    }

    int   id[4][4];
    float w[4][4];
    unsigned long long mask = 0ull;
#pragma unroll
    for (int k = 0; k < 4; ++k) {
        const int x = xs[k];
        const float fx = (x + 0.5f) * 0.0625f - 0.5f;
        const float x0f = floorf(fx);
        const float wx1 = fx - x0f, wx0 = 1.f - wx1;
        const int x0 = (int)x0f;
        const int xlo = max(x0, 0), xhi = min(x0 + 1, H_IN - 1);
        id[k][0] = __ldg(A0 + xlo); w[k][0] = wy0 * wx0;
        id[k][1] = __ldg(A0 + xhi); w[k][1] = wy0 * wx1;
        id[k][2] = __ldg(A1 + xlo); w[k][2] = wy1 * wx0;
        id[k][3] = __ldg(A1 + xhi); w[k][3] = wy1 * wx1;
        mask |= 1ull << id[k][0];
        mask |= 1ull << id[k][1];
        mask |= 1ull << id[k][2];
        mask |= 1ull << id[k][3];
    }

    float* base = out + 1 + (size_t)b * N_CLUS * PLANE + (size_t)y * OUT_HW;
    const int slot = 3 + 4 * tid;

#pragma unroll 4
    for (int n = 0; n < N_CLUS; ++n) {
        float4 v = make_float4(0.f, 0.f, 0.f, 0.f);
        if ((mask >> n) & 1ull) {
            float r[4];
#pragma unroll
            for (int k = 0; k < 4; ++k) {
                float s = 0.f;
#pragma unroll
                for (int q = 0; q < 4; ++q)
                    s += (id[k][q] == n) ? w[k][q] : 0.f;
                r[k] = s;
            }
            v = make_float4(r[0], r[1], r[2], r[3]);
        }
        float* row = base + (size_t)n * PLANE;
        if (tid < 127) {
            *(float4*)(row + slot) = v;      // plain STG.128
        } else {
            row[0] = v.x;
            row[1] = v.y;
            row[2] = v.z;
            row[511] = v.w;
        }
    }
}

// ---------------------------------------------------------------------------
// out layout = [loss(1)] [resized(134217728)] [code(6291456)]
// ---------------------------------------------------------------------------
extern "C" void kernel_launch(void* const* d_in, const int* in_sizes, int n_in,
                              void* d_out, int out_size) {
    const float* code = (const float*)d_in[0];
    const float* clusters = (const float*)d_in[1];
    float* out = (float*)d_out;

    normK<<<64, 256>>>(clusters);
    simPartK<<<512, 256>>>(code);
    writeK<<<W_BLOCKS, 128>>>(code, out);
}